// round 9
// baseline (speedup 1.0000x reference)
#include <cuda_runtime.h>
#include <cstdint>

// x:      (2, 64, 32, 32, 32) fp32
// weight: (64, 32, 3, 3, 3)   fp32
// bias:   (32,)               fp32
// out:    (2, 32, 66, 66, 66) fp32
//
// Core: out[n,co,2z+1] = bias[co] + sum_{ci,tap} W[ci,co,26-tap]*x[n,ci,z-1+k]
// All other outputs bias-only.
// Conv CTAs write the full [0,64)^3 region (bias at non-core positions);
// prep kernel writes only border slabs (any coord >= 64) + weight flip.

#define OUT_S 66
#define PLANE 4356            // 66*66
#define CH_STRIDE 287496      // 66^3
#define CIC 8
#define NCHUNK 8

// per-buffer smem: xs 8*10*10*10 floats = 32000 B, ws 8*27*32 = 27648 B
#define XS_BYTES 32000
#define BUF_BYTES 59648
#define SM_TOTAL (2 * BUF_BYTES)   // 119296

// Flipped weights staging: [ci][k][co], value = W[ci,co,26-k].
__device__ __align__(16) float g_wflip[64 * 27 * 32];

// prep kernel block roles
#define WPREP_BLOCKS 216           // 216*256 = 55296 elements
#define DHROW_BLOCKS 2080          // 16640 warps, one per border row
#define WPAIR_BLOCKS 1024          // 262144 threads, one (w=64,65) pair each
#define PREP_BLOCKS (WPREP_BLOCKS + DHROW_BLOCKS + WPAIR_BLOCKS)

// ---------------------------------------------------------------------------
// prep: (a) flip weights into g_wflip, (b) bias-fill border slabs of out.
// ---------------------------------------------------------------------------
__global__ void prep_kernel(const float* __restrict__ w,
                            const float* __restrict__ bias,
                            float* __restrict__ out) {
    const int b   = blockIdx.x;
    const int tid = threadIdx.x;
    if (b < WPREP_BLOCKS) {
        int i = b * 256 + tid;                 // 0..55295
        if (i < 55296) {
            int ci = i / 864;
            int r  = i - ci * 864;
            int k  = r >> 5;
            int co = r & 31;
            g_wflip[i] = w[(ci * 32 + co) * 27 + (26 - k)];
        }
    } else if (b < WPREP_BLOCKS + DHROW_BLOCKS) {
        // border rows: (ch, d, h) with d>=64 or h>=64; one warp per row
        int wg   = (b - WPREP_BLOCKS) * 8 + (tid >> 5);   // 0..16639
        int lane = tid & 31;
        int ch = wg / 260;
        int r  = wg - ch * 260;
        int d, h;
        if (r < 132) { d = 64 + (r >= 66 ? 1 : 0); h = r - (r >= 66 ? 66 : 0); }
        else         { int r2 = r - 132; d = r2 >> 1; h = 64 + (r2 & 1); }
        float bv = __ldg(&bias[ch & 31]);
        float* row = out + (size_t)ch * CH_STRIDE + (size_t)d * PLANE + h * OUT_S;
        for (int i = lane; i < OUT_S; i += 32) row[i] = bv;
    } else {
        // w-border pairs: d<64, h<64, w in {64,65}
        int idx = (b - WPREP_BLOCKS - DHROW_BLOCKS) * 256 + tid;  // 0..262143
        int ch  = idx >> 12;
        int rem = idx & 4095;
        int d   = rem >> 6;
        int h   = rem & 63;
        float bv = __ldg(&bias[ch & 31]);
        float2* p = (float2*)(out + (size_t)ch * CH_STRIDE
                              + (size_t)d * PLANE + h * OUT_S + 64);
        *p = make_float2(bv, bv);
    }
}

// ---------------------------------------------------------------------------
__device__ __forceinline__ void cp4_zfill(uint32_t saddr, const float* g, int ok) {
    asm volatile("cp.async.ca.shared.global [%0], [%1], 4, %2;"
                 :: "r"(saddr), "l"(g), "r"(ok ? 4 : 0) : "memory");
}
__device__ __forceinline__ void cp16(uint32_t saddr, const float4* g) {
    asm volatile("cp.async.cg.shared.global [%0], [%1], 16;"
                 :: "r"(saddr), "l"(g) : "memory");
}
__device__ __forceinline__ void cp_commit() {
    asm volatile("cp.async.commit_group;" ::: "memory");
}
template <int N>
__device__ __forceinline__ void cp_wait() {
    asm volatile("cp.async.wait_group %0;" :: "n"(N) : "memory");
}

// ---------------------------------------------------------------------------
// Block = 512 threads, (8,8,8) z-tile:
//   lw = tid&7, lh = (tid>>3)&7, ldd = (tid>>6)&1, coh = tid>>7 (co base 8*coh)
// Thread owns 4 points zloc = ldd + 2p (p<4) at (zh0+lh, zw0+lw), 8 co each.
// Inner loop per (ci, kh, kw): 9 LDS.32 (x planes, reused across kd) + 9 mov
// + 3 x (2 LDS.128 broadcast w) + 48 fma.rn.f32x2.
// Grid = (4,4,8) = 128 CTAs, one per SM. cp.async double-buffered chunks.
// Epilogue writes full 2x2x2 cubes (bias at non-core positions).
// ---------------------------------------------------------------------------
__global__ void __launch_bounds__(512, 1)
conv_core_kernel(const float* __restrict__ x,
                 const float* __restrict__ bias,
                 float* __restrict__ out) {
    extern __shared__ __align__(16) char smem[];
    uint32_t sb;
    asm("{ .reg .u64 t; cvta.to.shared.u64 t, %1; cvt.u32.u64 %0, t; }"
        : "=r"(sb) : "l"(smem));

    const int tid = threadIdx.x;
    const int lw  = tid & 7;
    const int lh  = (tid >> 3) & 7;
    const int ldd = (tid >> 6) & 1;
    const int coh = tid >> 7;                 // 0..3 -> co base 8*coh

    const int tw = blockIdx.x, th = blockIdx.y;
    const int nz = blockIdx.z;
    const int n  = nz >> 2;
    const int td = nz & 3;
    const int zd0 = td * 8, zh0 = th * 8, zw0 = tw * 8;

    const float* xn = x + (size_t)n * (64 * 32768);

    auto issue_chunk = [&](int cc, int buf) {
        uint32_t sx = sb + buf * BUF_BYTES;
#pragma unroll
        for (int j = 0; j < 16; ++j) {
            int i = tid + j * 512;
            if (i < 8000) {
                int ci = i / 1000;
                int r  = i - ci * 1000;
                int dd = r / 100;
                int r2 = r - dd * 100;
                int hh = r2 / 10;
                int ww = r2 - hh * 10;
                int gd = zd0 - 1 + dd;
                int gh = zh0 - 1 + hh;
                int gw = zw0 - 1 + ww;
                int ok = (gd >= 0 && gd < 32 && gh >= 0 && gh < 32 &&
                          gw >= 0 && gw < 32);
                const float* g = xn + (((size_t)(cc * CIC + ci) * 32 + (gd & 31))
                                       * 32 + (gh & 31)) * 32 + (gw & 31);
                cp4_zfill(sx + i * 4, g, ok);
            }
        }
        uint32_t sw = sx + XS_BYTES;
        const float4* gw4 = (const float4*)(g_wflip + cc * 6912);
#pragma unroll
        for (int j = 0; j < 4; ++j) {
            int i = tid + j * 512;
            if (i < 1728) cp16(sw + i * 16, gw4 + i);
        }
        cp_commit();
    };

    // acc[p][j] = point p, co pair {8coh+2j, 8coh+2j+1}
    unsigned long long acc[4][4];
#pragma unroll
    for (int p = 0; p < 4; ++p)
#pragma unroll
        for (int j = 0; j < 4; ++j) acc[p][j] = 0ull;

    issue_chunk(0, 0);

#pragma unroll 1
    for (int cc = 0; cc < NCHUNK; ++cc) {
        const int buf = cc & 1;
        if (cc + 1 < NCHUNK) {
            issue_chunk(cc + 1, buf ^ 1);
            cp_wait<1>();
        } else {
            cp_wait<0>();
        }
        __syncthreads();

        const float* xsb = (const float*)(smem + buf * BUF_BYTES);
        const float* wsb = (const float*)(smem + buf * BUF_BYTES + XS_BYTES);

#pragma unroll 1
        for (int ci = 0; ci < CIC; ++ci) {
            const float* xci = xsb + ci * 1000 + ldd * 100 + lh * 10 + lw;
            const float* wb  = wsb + ci * 27 * 32 + coh * 8;
#pragma unroll 1
            for (int kh = 0; kh < 3; ++kh) {
#pragma unroll 1
                for (int kw = 0; kw < 3; ++kw) {
                    const float* xr = xci + kh * 10 + kw;
                    // 9 x d-planes, reused across kd
                    unsigned long long xq2[9];
#pragma unroll
                    for (int i = 0; i < 9; ++i) {
                        float xv = xr[i * 100];
                        asm("mov.b64 %0, {%1, %1};" : "=l"(xq2[i]) : "f"(xv));
                    }
#pragma unroll
                    for (int kd = 0; kd < 3; ++kd) {
                        const ulonglong2* wr = (const ulonglong2*)
                            (wb + (kd * 9 + kh * 3 + kw) * 32);
                        ulonglong2 w0 = wr[0];   // co 8coh..+3 (broadcast)
                        ulonglong2 w1 = wr[1];   // co 8coh+4..+7
#pragma unroll
                        for (int p = 0; p < 4; ++p) {
                            unsigned long long xv2 = xq2[2 * p + kd];
                            asm("fma.rn.f32x2 %0, %1, %2, %0;"
                                : "+l"(acc[p][0]) : "l"(xv2), "l"(w0.x));
                            asm("fma.rn.f32x2 %0, %1, %2, %0;"
                                : "+l"(acc[p][1]) : "l"(xv2), "l"(w0.y));
                            asm("fma.rn.f32x2 %0, %1, %2, %0;"
                                : "+l"(acc[p][2]) : "l"(xv2), "l"(w1.x));
                            asm("fma.rn.f32x2 %0, %1, %2, %0;"
                                : "+l"(acc[p][3]) : "l"(xv2), "l"(w1.y));
                        }
                    }
                }
            }
        }
        __syncthreads();
    }

    // ---- epilogue: write full 2x2x2 cubes (7 bias + 1 core per point/co) ----
    float bv[8];
#pragma unroll
    for (int j = 0; j < 8; ++j) bv[j] = __ldg(&bias[coh * 8 + j]);

    const int ohe = 2 * (zh0 + lh);      // even h base
    const int owe = 2 * (zw0 + lw);      // even w base
#pragma unroll
    for (int p = 0; p < 4; ++p) {
        const int od = 2 * (zd0 + ldd + 2 * p);   // even d base
#pragma unroll
        for (int j = 0; j < 4; ++j) {
            float2 v;
            asm("mov.b64 {%0, %1}, %2;" : "=f"(v.x), "=f"(v.y)
                                        : "l"(acc[p][j]));
#pragma unroll
            for (int s = 0; s < 2; ++s) {
                const int co = coh * 8 + 2 * j + s;
                const float b  = bv[2 * j + s];
                const float cr = (s == 0 ? v.x : v.y) + b;
                float* base = out + (size_t)(n * 32 + co) * CH_STRIDE
                            + (size_t)od * PLANE + ohe * OUT_S + owe;
                float2 bb = make_float2(b, b);
                float2 bc = make_float2(b, cr);
                *(float2*)(base)                = bb;  // (od,   ohe,   w pair)
                *(float2*)(base + OUT_S)        = bb;  // (od,   ohe+1, w pair)
                *(float2*)(base + PLANE)        = bb;  // (od+1, ohe,   w pair)
                *(float2*)(base + PLANE + OUT_S) = bc; // (od+1, ohe+1, bias|core)
            }
        }
    }
}

// ---------------------------------------------------------------------------
extern "C" void kernel_launch(void* const* d_in, const int* in_sizes, int n_in,
                              void* d_out, int out_size) {
    const float* x = nullptr;
    const float* w = nullptr;
    const float* b = nullptr;
    for (int i = 0; i < n_in; ++i) {
        if (in_sizes[i] == 4194304)    x = (const float*)d_in[i];
        else if (in_sizes[i] == 55296) w = (const float*)d_in[i];
        else if (in_sizes[i] == 32)    b = (const float*)d_in[i];
    }
    float* out = (float*)d_out;

    cudaFuncSetAttribute(conv_core_kernel,
                         cudaFuncAttributeMaxDynamicSharedMemorySize, SM_TOTAL);

    prep_kernel<<<PREP_BLOCKS, 256>>>(w, b, out);

    dim3 grid(4, 4, 8);   // 128 CTAs = one per SM, single wave
    conv_core_kernel<<<grid, 512, SM_TOTAL>>>(x, b, out);
}